// round 14
// baseline (speedup 1.0000x reference)
#include <cuda_runtime.h>
#include <cuda_bf16.h>
#include <cstdint>
#include <math.h>

#define BATCH 16
#define LSEQ  8192
#define DDIM  256

#define KSPLIT 3
#define KC     32
#define NCHUNKS (LSEQ / KC)        // 256

// ---------------------------------------------------------------------------
// Static device scratch
// ---------------------------------------------------------------------------
__device__ float g_norm[BATCH * LSEQ];
__device__ float g_psum[BATCH * 64];
__device__ float g_sw[BATCH * LSEQ];
__device__ float g_part[BATCH * 3 * KSPLIT * 128 * 128];   // 9.4 MB
__device__ int   g_cnt[BATCH * 3];                         // finisher counters (0-init)

// ---------------------------------------------------------------------------
// Helpers
// ---------------------------------------------------------------------------
__device__ __forceinline__ uint32_t smem_u32(const void* p) {
    uint32_t a;
    asm("{ .reg .u64 t; cvta.to.shared.u64 t, %1; cvt.u32.u64 %0, t; }"
        : "=r"(a) : "l"(p));
    return a;
}

__device__ __forceinline__ void ldsm4t(uint32_t* r, uint32_t addr) {
    asm volatile("ldmatrix.sync.aligned.m8n8.x4.trans.shared.b16 {%0,%1,%2,%3}, [%4];"
                 : "=r"(r[0]), "=r"(r[1]), "=r"(r[2]), "=r"(r[3]) : "r"(addr));
}

__device__ __forceinline__ void mma16816(float* c, const uint32_t* a,
                                         uint32_t b0, uint32_t b1) {
    asm volatile(
        "mma.sync.aligned.m16n8k16.row.col.f32.bf16.bf16.f32 "
        "{%0,%1,%2,%3}, {%4,%5,%6,%7}, {%8,%9}, {%0,%1,%2,%3};"
        : "+f"(c[0]), "+f"(c[1]), "+f"(c[2]), "+f"(c[3])
        : "r"(a[0]), "r"(a[1]), "r"(a[2]), "r"(a[3]), "r"(b0), "r"(b1));
}

#define STS128(addr, r0, r1, r2, r3) \
    asm volatile("st.shared.v4.b32 [%0], {%1,%2,%3,%4};" \
                 :: "r"(addr), "r"(r0), "r"(r1), "r"(r2), "r"(r3))

__device__ __forceinline__ void split4(float4 v, float wv,
                                       uint32_t& h0, uint32_t& h1,
                                       uint32_t& lo0, uint32_t& lo1) {
    v.x *= wv; v.y *= wv; v.z *= wv; v.w *= wv;
    asm("cvt.rn.bf16x2.f32 %0, %1, %2;" : "=r"(h0) : "f"(v.y), "f"(v.x));
    asm("cvt.rn.bf16x2.f32 %0, %1, %2;" : "=r"(h1) : "f"(v.w), "f"(v.z));
    float r0 = v.x - __uint_as_float(h0 << 16);
    float r1 = v.y - __uint_as_float(h0 & 0xFFFF0000u);
    float r2 = v.z - __uint_as_float(h1 << 16);
    float r3 = v.w - __uint_as_float(h1 & 0xFFFF0000u);
    asm("cvt.rn.bf16x2.f32 %0, %1, %2;" : "=r"(lo0) : "f"(r1), "f"(r0));
    asm("cvt.rn.bf16x2.f32 %0, %1, %2;" : "=r"(lo1) : "f"(r3), "f"(r2));
}

// ---------------------------------------------------------------------------
// Stage A1: per-row L2 norms + per-block partial sums of exp(norm).
// ---------------------------------------------------------------------------
__global__ __launch_bounds__(256) void norms_kernel(const float* __restrict__ x)
{
    const int b    = blockIdx.y;
    const int r0   = blockIdx.x * 128;
    const int warp = threadIdx.x >> 5;
    const int lane = threadIdx.x & 31;
    const float* xb = x + (size_t)b * LSEQ * DDIM;

    __shared__ float sp[8];
    float esum = 0.f;

#pragma unroll 4
    for (int i = 0; i < 16; i++) {
        const int l = r0 + warp * 16 + i;
        const float4* row = (const float4*)(xb + (size_t)l * DDIM);
        float4 v1 = row[lane];
        float4 v2 = row[lane + 32];
        float s = v1.x * v1.x + v1.y * v1.y + v1.z * v1.z + v1.w * v1.w
                + v2.x * v2.x + v2.y * v2.y + v2.z * v2.z + v2.w * v2.w;
#pragma unroll
        for (int o = 16; o; o >>= 1) s += __shfl_xor_sync(0xffffffffu, s, o);
        if (lane == 0) {
            float n = sqrtf(s);
            g_norm[b * LSEQ + l] = n;
            esum += __expf(n);
        }
    }
    if (lane == 0) sp[warp] = esum;
    __syncthreads();
    if (warp == 0) {
        float t = (lane < 8) ? sp[lane] : 0.f;
#pragma unroll
        for (int o = 4; o; o >>= 1) t += __shfl_xor_sync(0xffffffffu, t, o);
        if (lane == 0) g_psum[b * 64 + blockIdx.x] = t;
    }
}

// ---------------------------------------------------------------------------
// Stage A2: sw = exp(n/2) / sqrt(S).  grid (32, 16).
// ---------------------------------------------------------------------------
__global__ __launch_bounds__(256) void scale_kernel()
{
    const int b   = blockIdx.y;
    const int tid = threadIdx.x;
    __shared__ float sred[2];

    if (tid < 64) {
        float t = g_psum[b * 64 + tid];
#pragma unroll
        for (int o = 16; o; o >>= 1) t += __shfl_xor_sync(0xffffffffu, t, o);
        if ((tid & 31) == 0) sred[tid >> 5] = t;
    }
    __syncthreads();
    const float rs = rsqrtf(sred[0] + sred[1]);

    const int l = blockIdx.x * 256 + tid;
    const float n = g_norm[b * LSEQ + l];
    g_sw[b * LSEQ + l] = __expf(0.5f * n) * rs;
}

// ---------------------------------------------------------------------------
// Stage B: bf16 hi/lo split SYRK; convert overlapped with MMA;
// 4-slot ring (barrier every 2 chunks); hi-fragment LDSM double-buffered
// across MMA steps; split-K reduce FUSED into the tail of the last CTA
// per (batch, tile).
// 512 threads (16 warps), occ 1, warp tile 32x32; grid (9,16) = one wave.
// ---------------------------------------------------------------------------
#define SP   136
#define SPB  272
#define ABYTES (KC * SPB)          // 8704
#define SLOT   (4 * ABYTES)        // 34816
#define SM_TOT (4 * SLOT)          // 139264

struct HiFrag { uint32_t ah0[4], ah1[4], bh0[4], bh1[4]; };

__global__ __launch_bounds__(512, 1) void tensor_gemm(const float* __restrict__ x,
                                                      float* __restrict__ out)
{
    extern __shared__ __align__(16) char dsm[];
    const uint32_t sb = smem_u32(dsm);

    const int tid  = threadIdx.x;
    const int wid  = tid >> 5;
    const int lane = tid & 31;

    const int tile = blockIdx.x / KSPLIT;   // 0:(0,0) 1:(0,1) 2:(1,1)
    const int s    = blockIdx.x % KSPLIT;
    const int b    = blockIdx.y;
    const int ti   = (tile == 2) ? 1 : 0;
    const int tj   = (tile >= 1) ? 1 : 0;
    const bool diag = (ti == tj);

    const float* xb  = x + (size_t)b * LSEQ * DDIM;
    const float* swb = g_sw + b * LSEQ;
    const int c0A = ti * 128;
    const int c0B = tj * 128;

    // chunk partition over 256: 86,85,85
    const int c_start = (s == 0) ? 0 : 86 + (s - 1) * 85;
    const int c_end   = c_start + ((s == 0) ? 86 : 85);

    const int wy = wid & 3;
    const int wx = wid >> 2;

    const uint32_t offA = ((lane & 7) + ((lane >> 4) & 1) * 8) * SPB
                        + ((lane >> 3) & 1) * 16 + (uint32_t)(wy * 64);
    const uint32_t offB = ((lane & 7) + ((lane >> 3) & 1) * 8) * SPB
                        + ((lane >> 4) & 1) * 16 + (uint32_t)(wx * 64);

    const int crow = wid * 2 + (lane >> 4);
    const int cq   = lane & 15;
    const uint32_t cvoff = (uint32_t)crow * SPB + (uint32_t)cq * 16;

    float acc[2][4][4];
#pragma unroll
    for (int m = 0; m < 2; m++)
#pragma unroll
        for (int n = 0; n < 4; n++)
#pragma unroll
            for (int q = 0; q < 4; q++) acc[m][n][q] = 0.f;

    float4 pa0, pa1, pb0, pb1;
    float  pw;
    HiFrag FC, FN;

#define SLOTADDR(cc) (sb + (uint32_t)((cc) & 3) * SLOT)

#define LOADREGS(cc) do { \
        const int l_ = (cc) * KC + crow; \
        pw = swb[l_]; \
        const float4* rp_ = (const float4*)(xb + (size_t)l_ * DDIM + c0A); \
        pa0 = rp_[cq * 2]; pa1 = rp_[cq * 2 + 1]; \
        if (!diag) { \
            const float4* rq_ = (const float4*)(xb + (size_t)l_ * DDIM + c0B); \
            pb0 = rq_[cq * 2]; pb1 = rq_[cq * 2 + 1]; \
        } \
    } while (0)

#define CONVREGS(base_) do { \
        const uint32_t yaH_ = (base_); \
        const uint32_t yaL_ = (base_) + ABYTES; \
        uint32_t h0, h1, h2, h3, q0, q1, q2, q3; \
        split4(pa0, pw, h0, h1, q0, q1); \
        split4(pa1, pw, h2, h3, q2, q3); \
        STS128(yaH_ + cvoff, h0, h1, h2, h3); \
        STS128(yaL_ + cvoff, q0, q1, q2, q3); \
        if (!diag) { \
            const uint32_t ybH_ = (base_) + 2 * ABYTES; \
            const uint32_t ybL_ = (base_) + 3 * ABYTES; \
            split4(pb0, pw, h0, h1, q0, q1); \
            split4(pb1, pw, h2, h3, q2, q3); \
            STS128(ybH_ + cvoff, h0, h1, h2, h3); \
            STS128(ybL_ + cvoff, q0, q1, q2, q3); \
        } \
    } while (0)

    // preload hi fragments (ah, bh) for (chunk cc, step kk)
#define LOADHI(F_, bM_, kk_) do { \
        const uint32_t yaH_ = (bM_); \
        const uint32_t ybH_ = diag ? yaH_ : (bM_) + 2 * ABYTES; \
        const uint32_t kr_  = (uint32_t)((kk_) * 16) * SPB; \
        ldsm4t((F_).ah0, yaH_ + offA + kr_); \
        ldsm4t((F_).ah1, yaH_ + offA + kr_ + 32); \
        ldsm4t((F_).bh0, ybH_ + offB + kr_); \
        ldsm4t((F_).bh1, ybH_ + offB + kr_ + 32); \
    } while (0)

    // consume preloaded hi frags; load lo frags inline; 24 MMAs
#define MMAHALF(F_, bM_, kk_) do { \
        const uint32_t yaL_ = (bM_) + ABYTES; \
        const uint32_t ybL_ = diag ? yaL_ : (bM_) + 3 * ABYTES; \
        const uint32_t kr_  = (uint32_t)((kk_) * 16) * SPB; \
        mma16816(acc[0][0], (F_).ah0, (F_).bh0[0], (F_).bh0[1]); \
        mma16816(acc[0][1], (F_).ah0, (F_).bh0[2], (F_).bh0[3]); \
        mma16816(acc[0][2], (F_).ah0, (F_).bh1[0], (F_).bh1[1]); \
        mma16816(acc[0][3], (F_).ah0, (F_).bh1[2], (F_).bh1[3]); \
        mma16816(acc[1][0], (F_).ah1, (F_).bh0[0], (F_).bh0[1]); \
        mma16816(acc[1][1], (F_).ah1, (F_).bh0[2], (F_).bh0[3]); \
        mma16816(acc[1][2], (F_).ah1, (F_).bh1[0], (F_).bh1[1]); \
        mma16816(acc[1][3], (F_).ah1, (F_).bh1[2], (F_).bh1[3]); \
        { \
            uint32_t x0[4], x1[4]; \
            ldsm4t(x0, ybL_ + offB + kr_); \
            ldsm4t(x1, ybL_ + offB + kr_ + 32); \
            mma16816(acc[0][0], (F_).ah0, x0[0], x0[1]); \
            mma16816(acc[0][1], (F_).ah0, x0[2], x0[3]); \
            mma16816(acc[0][2], (F_).ah0, x1[0], x1[1]); \
            mma16816(acc[0][3], (F_).ah0, x1[2], x1[3]); \
            mma16816(acc[1][0], (F_).ah1, x0[0], x0[1]); \
            mma16816(acc[1][1], (F_).ah1, x0[2], x0[3]); \
            mma16816(acc[1][2], (F_).ah1, x1[0], x1[1]); \
            mma16816(acc[1][3], (F_).ah1, x1[2], x1[3]); \
            ldsm4t(x0, yaL_ + offA + kr_); \
            ldsm4t(x1, yaL_ + offA + kr_ + 32); \
            mma16816(acc[0][0], x0, (F_).bh0[0], (F_).bh0[1]); \
            mma16816(acc[0][1], x0, (F_).bh0[2], (F_).bh0[3]); \
            mma16816(acc[0][2], x0, (F_).bh1[0], (F_).bh1[1]); \
            mma16816(acc[0][3], x0, (F_).bh1[2], (F_).bh1[3]); \
            mma16816(acc[1][0], x1, (F_).bh0[0], (F_).bh0[1]); \
            mma16816(acc[1][1], x1, (F_).bh0[2], (F_).bh0[3]); \
            mma16816(acc[1][2], x1, (F_).bh1[0], (F_).bh1[1]); \
            mma16816(acc[1][3], x1, (F_).bh1[2], (F_).bh1[3]); \
        } \
    } while (0)

    // -------- prologue: convert c_start, c_start+1; LDG c_start+2 ----
    LOADREGS(c_start);
    CONVREGS(SLOTADDR(c_start));
    if (c_start + 1 < c_end) {
        LOADREGS(c_start + 1);
        CONVREGS(SLOTADDR(c_start + 1));
    }
    if (c_start + 2 < c_end) LOADREGS(c_start + 2);
    __syncthreads();
    LOADHI(FC, SLOTADDR(c_start), 0);

    for (int c = c_start; c < c_end; c++) {
        const uint32_t bM = SLOTADDR(c);

        LOADHI(FN, bM, 1);            // prefetch step k1 of this chunk
        MMAHALF(FC, bM, 0);

        if (c + 2 < c_end) CONVREGS(SLOTADDR(c + 2));
        if (c + 3 < c_end) LOADREGS(c + 3);

        const bool nb = ((c - c_start) & 1) == 0;   // no barrier after this chunk
        if (nb && c + 1 < c_end)
            LOADHI(FC, SLOTADDR(c + 1), 0);          // prefetch across chunk boundary

        MMAHALF(FN, bM, 1);

        if (!nb) {
            __syncthreads();
            if (c + 1 < c_end) LOADHI(FC, SLOTADDR(c + 1), 0);
        }
    }

    // ---- epilogue: write split-K partial tile ----
    float* dst = g_part + (((size_t)b * 3 + tile) * KSPLIT + s) * (128 * 128);
#pragma unroll
    for (int m = 0; m < 2; m++)
#pragma unroll
        for (int j = 0; j < 2; j++)
#pragma unroll
            for (int n = 0; n < 2; n++) {
                const int d = wy * 32 + m * 16 + (lane >> 2);
                const int e = wx * 32 + j * 16 + n * 8 + (lane & 3) * 2;
                float* cc = acc[m][j * 2 + n];
                *(float2*)(dst + d * 128 + e)       = make_float2(cc[0], cc[1]);
                *(float2*)(dst + (d + 8) * 128 + e) = make_float2(cc[2], cc[3]);
            }

    // ---- fused split-K reduce: last CTA per (b, tile) sums partials ----
    __threadfence();
    __shared__ int is_last;
    if (tid == 0) {
        int old = atomicAdd(&g_cnt[b * 3 + tile], 1);
        is_last = (old == KSPLIT - 1) ? 1 : 0;
    }
    __syncthreads();
    if (is_last) {
        __threadfence();   // acquire: pair with producers' release fences
        const float* p = g_part + (((size_t)b * 3 + tile) * KSPLIT) * 16384;
        float* ob = out + (size_t)b * DDIM * DDIM;
        for (int i = tid * 4; i < 16384; i += 512 * 4) {
            float4 v0 = *(const float4*)(p + i);
            float4 v1 = *(const float4*)(p + 16384 + i);
            float4 v2 = *(const float4*)(p + 32768 + i);
            float4 v = make_float4(v0.x + v1.x + v2.x, v0.y + v1.y + v2.y,
                                   v0.z + v1.z + v2.z, v0.w + v1.w + v2.w);
            const int dl = i >> 7, el = i & 127;
            if (tile == 0) {
                *(float4*)(ob + (size_t)dl * DDIM + el) = v;
            } else if (tile == 2) {
                *(float4*)(ob + (size_t)(128 + dl) * DDIM + 128 + el) = v;
            } else {
                *(float4*)(ob + (size_t)dl * DDIM + 128 + el) = v;
                ob[(size_t)(128 + el + 0) * DDIM + dl] = v.x;
                ob[(size_t)(128 + el + 1) * DDIM + dl] = v.y;
                ob[(size_t)(128 + el + 2) * DDIM + dl] = v.z;
                ob[(size_t)(128 + el + 3) * DDIM + dl] = v.w;
            }
        }
        if (tid == 0) atomicExch(&g_cnt[b * 3 + tile], 0);   // reset for next replay
    }

#undef LOADREGS
#undef CONVREGS
#undef LOADHI
#undef MMAHALF
#undef SLOTADDR
}

// ---------------------------------------------------------------------------
extern "C" void kernel_launch(void* const* d_in, const int* in_sizes, int n_in,
                              void* d_out, int out_size)
{
    const float* x = (const float*)d_in[0];
    float* out = (float*)d_out;

    cudaFuncSetAttribute(tensor_gemm, cudaFuncAttributeMaxDynamicSharedMemorySize, SM_TOT);

    norms_kernel<<<dim3(64, BATCH), 256>>>(x);
    scale_kernel<<<dim3(32, BATCH), 256>>>();
    tensor_gemm<<<dim3(3 * KSPLIT, BATCH), 512, SM_TOT>>>(x, out);
}